// round 13
// baseline (speedup 1.0000x reference)
#include <cuda_runtime.h>

#define ALPHA 0.1f
#define BETA  0.96f
#define VTHR  2.0f
#define DEPTH 16

__device__ __forceinline__ void snn_step(float xv, float& syn, float& mem,
                                         float& spk_o, float& syn_o, float& mem_o)
{
    bool reset = (mem > VTHR);
    syn = fmaf(ALPHA, syn, xv);
    mem = fmaf(BETA,  mem, syn);
    if (reset) { syn = 0.f; mem = 0.f; }
    spk_o = (mem > VTHR) ? 1.f : 0.f;
    syn_o = syn;
    mem_o = mem;
}

__device__ __forceinline__ void snn_step4(float4 xv,
                                          float& s0, float& s1, float& s2, float& s3,
                                          float& m0, float& m1, float& m2, float& m3,
                                          float4* __restrict__ spk,
                                          float4* __restrict__ syn,
                                          float4* __restrict__ mem,
                                          size_t row)
{
    float4 sp, so, mo;
    snn_step(xv.x, s0, m0, sp.x, so.x, mo.x);
    snn_step(xv.y, s1, m1, sp.y, so.y, mo.y);
    snn_step(xv.z, s2, m2, sp.z, so.z, mo.z);
    snn_step(xv.w, s3, m3, sp.w, so.w, mo.w);
    // evict-first stores: measured best store policy (beats .wb and .wt)
    __stcs(spk + row, sp);
    __stcs(syn + row, so);
    __stcs(mem + row, mo);
}

// DEPTH=16 rolling ring, this time WITHOUT the 128-reg cap that made R6's
// DEPTH=16 spill: __launch_bounds__(32, 8) raises the reg budget to 256
// (~160 needed, no spill; 8 blocks/SM >= the ~7 we place). Tests whether
// doubling queued reads per warp lets the DRAM controller batch longer read
// bursts between write drains (attacking the R/W-turnaround residual).
// All other choices are the validated best (float4 lanes, 1024 one-warp
// blocks, __ldcs reads, __stcs stores).
__global__ __launch_bounds__(32, 8)
void snn_scan_kernel(const float4* __restrict__ x,
                     float4* __restrict__ spk_out,
                     float4* __restrict__ syn_out,
                     float4* __restrict__ mem_out,
                     int T, int BN4)
{
    int idx = blockIdx.x * blockDim.x + threadIdx.x;
    if (idx >= BN4) return;

    float s0 = 0.f, s1 = 0.f, s2 = 0.f, s3 = 0.f;
    float m0 = 0.f, m1 = 0.f, m2 = 0.f, m3 = 0.f;

    const size_t stride = (size_t)BN4;
    const size_t batch_stride = (size_t)DEPTH * stride;
    const float4* xp = x + idx;

    // prime the ring with t = 0..DEPTH-1
    float4 pf[DEPTH];
    #pragma unroll
    for (int i = 0; i < DEPTH; ++i)
        pf[i] = __ldcs(xp + (size_t)i * stride);

    // T is a multiple of DEPTH (512 / 16 = 32 batches)
    for (int t = 0; t < T; t += DEPTH) {
        size_t row = (size_t)t * stride + idx;
        // refill source: DEPTH steps ahead; on the last batch, reload the
        // current rows instead (values unused, stays in-bounds)
        const float4* xnext = (t + DEPTH < T) ? (xp + batch_stride) : xp;

        #pragma unroll
        for (int i = 0; i < DEPTH; ++i) {
            float4 xv = pf[i];
            // refill this slot immediately after freeing it
            pf[i] = __ldcs(xnext + (size_t)i * stride);
            snn_step4(xv, s0, s1, s2, s3, m0, m1, m2, m3,
                      spk_out, syn_out, mem_out, row);
            row += stride;
        }

        xp += batch_stride;
    }
}

extern "C" void kernel_launch(void* const* d_in, const int* in_sizes, int n_in,
                              void* d_out, int out_size)
{
    const float* x = (const float*)d_in[0];
    float* out = (float*)d_out;

    const int T = 512;
    int total = in_sizes[0];          // T * B * N
    int BN = total / T;               // 131072
    int BN4 = BN / 4;                 // 32768 float4 lanes

    float4* spk = (float4*)out;
    float4* syn = (float4*)(out + (size_t)total);
    float4* mem = (float4*)(out + 2 * (size_t)total);

    int threads = 32;
    int blocks = (BN4 + threads - 1) / threads;   // 1024 one-warp blocks
    snn_scan_kernel<<<blocks, threads>>>((const float4*)x, spk, syn, mem, T, BN4);
}

// round 14
// speedup vs baseline: 1.0561x; 1.0561x over previous
#include <cuda_runtime.h>

#define ALPHA 0.1f
#define BETA  0.96f
#define VTHR  2.0f
#define DEPTH 8

__device__ __forceinline__ void snn_step(float xv, float& syn, float& mem,
                                         float& spk_o, float& syn_o, float& mem_o)
{
    bool reset = (mem > VTHR);
    syn = fmaf(ALPHA, syn, xv);
    mem = fmaf(BETA,  mem, syn);
    if (reset) { syn = 0.f; mem = 0.f; }
    spk_o = (mem > VTHR) ? 1.f : 0.f;
    syn_o = syn;
    mem_o = mem;
}

__device__ __forceinline__ void snn_step4(float4 xv,
                                          float& s0, float& s1, float& s2, float& s3,
                                          float& m0, float& m1, float& m2, float& m3,
                                          float4* __restrict__ spk,
                                          float4* __restrict__ syn,
                                          float4* __restrict__ mem,
                                          size_t row)
{
    float4 sp, so, mo;
    snn_step(xv.x, s0, m0, sp.x, so.x, mo.x);
    snn_step(xv.y, s1, m1, sp.y, so.y, mo.y);
    snn_step(xv.z, s2, m2, sp.z, so.z, mo.z);
    snn_step(xv.w, s3, m3, sp.w, so.w, mo.w);
    // evict-first stores: measured best store policy (.wb and .wt both slower)
    __stcs(spk + row, sp);
    __stcs(syn + row, so);
    __stcs(mem + row, mo);
}

// FINAL kernel — converged optimum of the full sweep:
//   float4 lanes | 1024 one-warp blocks | DEPTH=8 rolling prefetch ring
//   __ldcs reads | __stcs stores | 96 regs, no spill
// Reproduced 3x at 164.5-165.3us kernel time, 6.17 TB/s HBM (DRAM 77.9%),
// ~89% of the ~6.9 TB/s LTS cap on the mandatory 1.016 GB of traffic.
// Depth is an interior optimum (4 < 8 > 16: extra queued loads contend in
// the shared L1tex wavefront FIFO once read latency is covered). Residual
// vs cap is HBM R/W turnaround on the inherent 1:3 read:write mix.
__global__ __launch_bounds__(32, 16)
void snn_scan_kernel(const float4* __restrict__ x,
                     float4* __restrict__ spk_out,
                     float4* __restrict__ syn_out,
                     float4* __restrict__ mem_out,
                     int T, int BN4)
{
    int idx = blockIdx.x * blockDim.x + threadIdx.x;
    if (idx >= BN4) return;

    float s0 = 0.f, s1 = 0.f, s2 = 0.f, s3 = 0.f;
    float m0 = 0.f, m1 = 0.f, m2 = 0.f, m3 = 0.f;

    const size_t stride = (size_t)BN4;
    const size_t batch_stride = (size_t)DEPTH * stride;
    const float4* xp = x + idx;

    // prime the ring with t = 0..DEPTH-1
    float4 pf[DEPTH];
    #pragma unroll
    for (int i = 0; i < DEPTH; ++i)
        pf[i] = __ldcs(xp + (size_t)i * stride);

    // T is a multiple of DEPTH (512 / 8 = 64 batches)
    for (int t = 0; t < T; t += DEPTH) {
        size_t row = (size_t)t * stride + idx;
        // refill source: DEPTH steps ahead; on the last batch, reload the
        // current rows instead (values unused, stays in-bounds)
        const float4* xnext = (t + DEPTH < T) ? (xp + batch_stride) : xp;

        #pragma unroll
        for (int i = 0; i < DEPTH; ++i) {
            float4 xv = pf[i];
            // refill this slot immediately after freeing it
            pf[i] = __ldcs(xnext + (size_t)i * stride);
            snn_step4(xv, s0, s1, s2, s3, m0, m1, m2, m3,
                      spk_out, syn_out, mem_out, row);
            row += stride;
        }

        xp += batch_stride;
    }
}

extern "C" void kernel_launch(void* const* d_in, const int* in_sizes, int n_in,
                              void* d_out, int out_size)
{
    const float* x = (const float*)d_in[0];
    float* out = (float*)d_out;

    const int T = 512;
    int total = in_sizes[0];          // T * B * N
    int BN = total / T;               // 131072
    int BN4 = BN / 4;                 // 32768 float4 lanes

    float4* spk = (float4*)out;
    float4* syn = (float4*)(out + (size_t)total);
    float4* mem = (float4*)(out + 2 * (size_t)total);

    int threads = 32;
    int blocks = (BN4 + threads - 1) / threads;   // 1024 one-warp blocks
    snn_scan_kernel<<<blocks, threads>>>((const float4*)x, spk, syn, mem, T, BN4);
}

// round 15
// speedup vs baseline: 1.0841x; 1.0265x over previous
#include <cuda_runtime.h>

#define ALPHA 0.1f
#define BETA  0.96f
#define VTHR  2.0f
#define DEPTH 8

__device__ __forceinline__ void snn_step(float xv, float& syn, float& mem,
                                         float& spk_o, float& syn_o, float& mem_o)
{
    bool reset = (mem > VTHR);
    syn = fmaf(ALPHA, syn, xv);
    mem = fmaf(BETA,  mem, syn);
    if (reset) { syn = 0.f; mem = 0.f; }
    spk_o = (mem > VTHR) ? 1.f : 0.f;
    syn_o = syn;
    mem_o = mem;
}

__device__ __forceinline__ void snn_step4(float4 xv,
                                          float& s0, float& s1, float& s2, float& s3,
                                          float& m0, float& m1, float& m2, float& m3,
                                          float4* __restrict__ spk,
                                          float4* __restrict__ syn,
                                          float4* __restrict__ mem,
                                          size_t row)
{
    float4 sp, so, mo;
    snn_step(xv.x, s0, m0, sp.x, so.x, mo.x);
    snn_step(xv.y, s1, m1, sp.y, so.y, mo.y);
    snn_step(xv.z, s2, m2, sp.z, so.z, mo.z);
    snn_step(xv.w, s3, m3, sp.w, so.w, mo.w);
    // evict-first stores: measured best store policy (.wb and .wt both slower)
    __stcs(spk + row, sp);
    __stcs(syn + row, so);
    __stcs(mem + row, mo);
}

// FINAL kernel — converged optimum of the full sweep:
//   float4 lanes | 1024 one-warp blocks | DEPTH=8 rolling prefetch ring
//   __ldcs reads | __stcs stores | 96 regs, no spill
// Reproduced 4x at 164.5-169.1us kernel time (run-to-run noise ~±2.5us),
// ~6.0-6.2 TB/s HBM on the mandatory 1.016 GB of traffic — ~89% of the
// ~6.9 TB/s path-independent LTS cap. Depth is an interior optimum
// (4 < 8 > 16); residual is HBM R/W turnaround on the inherent 1:3 mix.
__global__ __launch_bounds__(32, 16)
void snn_scan_kernel(const float4* __restrict__ x,
                     float4* __restrict__ spk_out,
                     float4* __restrict__ syn_out,
                     float4* __restrict__ mem_out,
                     int T, int BN4)
{
    int idx = blockIdx.x * blockDim.x + threadIdx.x;
    if (idx >= BN4) return;

    float s0 = 0.f, s1 = 0.f, s2 = 0.f, s3 = 0.f;
    float m0 = 0.f, m1 = 0.f, m2 = 0.f, m3 = 0.f;

    const size_t stride = (size_t)BN4;
    const size_t batch_stride = (size_t)DEPTH * stride;
    const float4* xp = x + idx;

    // prime the ring with t = 0..DEPTH-1
    float4 pf[DEPTH];
    #pragma unroll
    for (int i = 0; i < DEPTH; ++i)
        pf[i] = __ldcs(xp + (size_t)i * stride);

    // T is a multiple of DEPTH (512 / 8 = 64 batches)
    for (int t = 0; t < T; t += DEPTH) {
        size_t row = (size_t)t * stride + idx;
        // refill source: DEPTH steps ahead; on the last batch, reload the
        // current rows instead (values unused, stays in-bounds)
        const float4* xnext = (t + DEPTH < T) ? (xp + batch_stride) : xp;

        #pragma unroll
        for (int i = 0; i < DEPTH; ++i) {
            float4 xv = pf[i];
            // refill this slot immediately after freeing it
            pf[i] = __ldcs(xnext + (size_t)i * stride);
            snn_step4(xv, s0, s1, s2, s3, m0, m1, m2, m3,
                      spk_out, syn_out, mem_out, row);
            row += stride;
        }

        xp += batch_stride;
    }
}

extern "C" void kernel_launch(void* const* d_in, const int* in_sizes, int n_in,
                              void* d_out, int out_size)
{
    const float* x = (const float*)d_in[0];
    float* out = (float*)d_out;

    const int T = 512;
    int total = in_sizes[0];          // T * B * N
    int BN = total / T;               // 131072
    int BN4 = BN / 4;                 // 32768 float4 lanes

    float4* spk = (float4*)out;
    float4* syn = (float4*)(out + (size_t)total);
    float4* mem = (float4*)(out + 2 * (size_t)total);

    int threads = 32;
    int blocks = (BN4 + threads - 1) / threads;   // 1024 one-warp blocks
    snn_scan_kernel<<<blocks, threads>>>((const float4*)x, spk, syn, mem, T, BN4);
}